// round 10
// baseline (speedup 1.0000x reference)
#include <cuda_runtime.h>
#include <math_constants.h>

// GraphSAGE fused: masked-max aggregation + relu + concat + Linear.
// B=4, N=512, C=128, OUT=128, adj ~10% dense (0.0/1.0 floats).
//
// R10: warp-specialized phase overlap.
//  - warps 0-7: aggregation, 1 warp per row (full adjacency row,
//    ballot-compact + MLP=8 float4 gather), relu'd result -> aggbuf.
//  - warps 8-15 (concurrently): stage featT (k-major feat half of combT),
//    named-barrier among themselves, then feat-half GEMM (k in [0,128),
//    2-way k-split, W[0:128) read exactly once per block).
//  - join sync; all warps build neigh half of combT; neigh-half GEMM
//    (k in [128,256), 4-way k-split, W[128:256) once per block).
//  - final: 1024 outputs = bias + 2 feat partials + 4 neigh partials.
// GEMM inner loops use packed fma.rn.f32x2 on row pairs (R9-proven).

#define B_DIM 4
#define N_DIM 512
#define C_DIM 128
#define OUT_DIM 128
#define ROWS 8
#define THREADS 512

__global__ __launch_bounds__(THREADS, 2)
void graphsage_fused_kernel(const float* __restrict__ adj,
                            const float* __restrict__ feat,
                            const float* __restrict__ W,
                            const float* __restrict__ bias,
                            float* __restrict__ out)
{
    __shared__ __align__(16) float combT[2 * C_DIM][ROWS];      // 8 KB
    __shared__ __align__(16) float ps_feat[2][ROWS][OUT_DIM];   // 8 KB
    __shared__ __align__(16) float ps_ngh[4][ROWS][OUT_DIM];    // 16 KB
    __shared__ __align__(16) float aggbuf[ROWS][C_DIM];         // 4 KB
    __shared__ __align__(16) unsigned short idxbuf[ROWS][520];  // 8.1 KB

    const int tid  = threadIdx.x;
    const int warp = tid >> 5;
    const int lane = tid & 31;

    const int block_row0 = blockIdx.x * ROWS;

    if (warp < 8) {
        // ================= aggregation: warp w owns row w =================
        const int row  = warp;
        const int grow = block_row0 + row;
        const int b = grow >> 9;
        const int i = grow & (N_DIM - 1);

        const float* __restrict__ fb = feat + (size_t)b * N_DIM * C_DIM;
        const float* __restrict__ adjrow = adj + ((size_t)b * N_DIM + i) * N_DIM;

        unsigned short* __restrict__ myidx = idxbuf[row];
        const unsigned lt = (1u << lane) - 1u;

        int total = 0;
        #pragma unroll
        for (int c = 0; c < N_DIM; c += 128) {
            float4 a = reinterpret_cast<const float4*>(adjrow + c)[lane];
            const int cbase = c + 4 * lane;
            {
                unsigned m = __ballot_sync(0xffffffffu, a.x > 0.0f);
                if (a.x > 0.0f) myidx[total + __popc(m & lt)] = (unsigned short)(cbase + 0);
                total += __popc(m);
            }
            {
                unsigned m = __ballot_sync(0xffffffffu, a.y > 0.0f);
                if (a.y > 0.0f) myidx[total + __popc(m & lt)] = (unsigned short)(cbase + 1);
                total += __popc(m);
            }
            {
                unsigned m = __ballot_sync(0xffffffffu, a.z > 0.0f);
                if (a.z > 0.0f) myidx[total + __popc(m & lt)] = (unsigned short)(cbase + 2);
                total += __popc(m);
            }
            {
                unsigned m = __ballot_sync(0xffffffffu, a.w > 0.0f);
                if (a.w > 0.0f) myidx[total + __popc(m & lt)] = (unsigned short)(cbase + 3);
                total += __popc(m);
            }
        }
        __syncwarp();

        float4 acc0 = make_float4(-CUDART_INF_F, -CUDART_INF_F, -CUDART_INF_F, -CUDART_INF_F);
        float4 acc1 = acc0, acc2 = acc0, acc3 = acc0;

        if (total > 0) {
            const int padded = (total + 7) & ~7;
            unsigned short lastv = myidx[total - 1];
            __syncwarp();
            if (lane < padded - total) myidx[total + lane] = lastv;
            __syncwarp();

            const uint4* __restrict__ ivec = reinterpret_cast<const uint4*>(myidx);
            for (int k = 0; k < padded; k += 8) {
                uint4 I = ivec[k >> 3];
                int j0 =  I.x        & 0xffff;
                int j1 = (I.x >> 16) & 0xffff;
                int j2 =  I.y        & 0xffff;
                int j3 = (I.y >> 16) & 0xffff;
                int j4 =  I.z        & 0xffff;
                int j5 = (I.z >> 16) & 0xffff;
                int j6 =  I.w        & 0xffff;
                int j7 = (I.w >> 16) & 0xffff;

                float4 f0 = reinterpret_cast<const float4*>(fb + (size_t)j0 * C_DIM)[lane];
                float4 f1 = reinterpret_cast<const float4*>(fb + (size_t)j1 * C_DIM)[lane];
                float4 f2 = reinterpret_cast<const float4*>(fb + (size_t)j2 * C_DIM)[lane];
                float4 f3 = reinterpret_cast<const float4*>(fb + (size_t)j3 * C_DIM)[lane];
                float4 f4 = reinterpret_cast<const float4*>(fb + (size_t)j4 * C_DIM)[lane];
                float4 f5 = reinterpret_cast<const float4*>(fb + (size_t)j5 * C_DIM)[lane];
                float4 f6 = reinterpret_cast<const float4*>(fb + (size_t)j6 * C_DIM)[lane];
                float4 f7 = reinterpret_cast<const float4*>(fb + (size_t)j7 * C_DIM)[lane];

                acc0.x = fmaxf(acc0.x, f0.x); acc0.y = fmaxf(acc0.y, f0.y);
                acc0.z = fmaxf(acc0.z, f0.z); acc0.w = fmaxf(acc0.w, f0.w);
                acc1.x = fmaxf(acc1.x, f1.x); acc1.y = fmaxf(acc1.y, f1.y);
                acc1.z = fmaxf(acc1.z, f1.z); acc1.w = fmaxf(acc1.w, f1.w);
                acc2.x = fmaxf(acc2.x, f2.x); acc2.y = fmaxf(acc2.y, f2.y);
                acc2.z = fmaxf(acc2.z, f2.z); acc2.w = fmaxf(acc2.w, f2.w);
                acc3.x = fmaxf(acc3.x, f3.x); acc3.y = fmaxf(acc3.y, f3.y);
                acc3.z = fmaxf(acc3.z, f3.z); acc3.w = fmaxf(acc3.w, f3.w);

                acc0.x = fmaxf(acc0.x, f4.x); acc0.y = fmaxf(acc0.y, f4.y);
                acc0.z = fmaxf(acc0.z, f4.z); acc0.w = fmaxf(acc0.w, f4.w);
                acc1.x = fmaxf(acc1.x, f5.x); acc1.y = fmaxf(acc1.y, f5.y);
                acc1.z = fmaxf(acc1.z, f5.z); acc1.w = fmaxf(acc1.w, f5.w);
                acc2.x = fmaxf(acc2.x, f6.x); acc2.y = fmaxf(acc2.y, f6.y);
                acc2.z = fmaxf(acc2.z, f6.z); acc2.w = fmaxf(acc2.w, f6.w);
                acc3.x = fmaxf(acc3.x, f7.x); acc3.y = fmaxf(acc3.y, f7.y);
                acc3.z = fmaxf(acc3.z, f7.z); acc3.w = fmaxf(acc3.w, f7.w);
            }
        }

        float4 nb;
        nb.x = fmaxf(0.0f, fmaxf(fmaxf(acc0.x, acc1.x), fmaxf(acc2.x, acc3.x)));
        nb.y = fmaxf(0.0f, fmaxf(fmaxf(acc0.y, acc1.y), fmaxf(acc2.y, acc3.y)));
        nb.z = fmaxf(0.0f, fmaxf(fmaxf(acc0.z, acc1.z), fmaxf(acc2.z, acc3.z)));
        nb.w = fmaxf(0.0f, fmaxf(fmaxf(acc0.w, acc1.w), fmaxf(acc2.w, acc3.w)));
        reinterpret_cast<float4*>(&aggbuf[row][0])[lane] = nb;
    } else {
        // ======= staging + feat-half GEMM (runs under the aggregation) =====
        const int t2 = tid - 256;            // 0..255

        // stage featT: r = t2&7, c = (t2>>3) + 32j  (conflict-free STS)
        {
            const int r  = t2 & 7;
            const int cb0 = t2 >> 3;         // 0..31
            const int gr = block_row0 + r;
            const int rb = gr >> 9;
            const int ri = gr & (N_DIM - 1);
            const float* __restrict__ frow =
                feat + ((size_t)rb * N_DIM + ri) * C_DIM;
            #pragma unroll
            for (int j = 0; j < 4; ++j) {
                const int c = cb0 + 32 * j;
                combT[c][r] = frow[c];
            }
        }
        // named barrier among the 8 staging warps only
        asm volatile("bar.sync 1, 256;" ::: "memory");

        // feat-half GEMM: o = t2&127, g = t2>>7 (2-way split of k in [0,128))
        {
            const int o = t2 & (OUT_DIM - 1);
            const int g = t2 >> 7;

            const float* __restrict__ wp = W + (size_t)(g * 64) * OUT_DIM + o;
            const float* __restrict__ cb = &combT[g * 64][0];

            unsigned long long a01 = 0ull, a23 = 0ull, a45 = 0ull, a67 = 0ull;

            #pragma unroll 8
            for (int k = 0; k < 64; ++k) {
                float w = wp[(size_t)k * OUT_DIM];
                unsigned long long wpk;
                asm("mov.b64 %0, {%1, %1};" : "=l"(wpk) : "f"(w));

                const double2 q0 = *reinterpret_cast<const double2*>(cb + k * 8);
                const double2 q1 = *reinterpret_cast<const double2*>(cb + k * 8 + 4);
                unsigned long long p01 = __double_as_longlong(q0.x);
                unsigned long long p23 = __double_as_longlong(q0.y);
                unsigned long long p45 = __double_as_longlong(q1.x);
                unsigned long long p67 = __double_as_longlong(q1.y);

                asm("fma.rn.f32x2 %0, %1, %2, %0;" : "+l"(a01) : "l"(p01), "l"(wpk));
                asm("fma.rn.f32x2 %0, %1, %2, %0;" : "+l"(a23) : "l"(p23), "l"(wpk));
                asm("fma.rn.f32x2 %0, %1, %2, %0;" : "+l"(a45) : "l"(p45), "l"(wpk));
                asm("fma.rn.f32x2 %0, %1, %2, %0;" : "+l"(a67) : "l"(p67), "l"(wpk));
            }

            float r0, r1, r2, r3, r4, r5, r6, r7;
            asm("mov.b64 {%0, %1}, %2;" : "=f"(r0), "=f"(r1) : "l"(a01));
            asm("mov.b64 {%0, %1}, %2;" : "=f"(r2), "=f"(r3) : "l"(a23));
            asm("mov.b64 {%0, %1}, %2;" : "=f"(r4), "=f"(r5) : "l"(a45));
            asm("mov.b64 {%0, %1}, %2;" : "=f"(r6), "=f"(r7) : "l"(a67));

            float* p = &ps_feat[g][0][o];
            p[0 * OUT_DIM] = r0;  p[1 * OUT_DIM] = r1;
            p[2 * OUT_DIM] = r2;  p[3 * OUT_DIM] = r3;
            p[4 * OUT_DIM] = r4;  p[5 * OUT_DIM] = r5;
            p[6 * OUT_DIM] = r6;  p[7 * OUT_DIM] = r7;
        }
    }

    __syncthreads();   // join: aggbuf + ps_feat ready

    // ---- build neigh half of combT (all 512 threads) ----
    {
        const int r  = tid & 7;
        const int c8 = tid >> 3;       // 0..63
        #pragma unroll
        for (int j = 0; j < 2; ++j) {
            const int c = c8 + 64 * j;
            combT[C_DIM + c][r] = aggbuf[r][c];
        }
    }
    __syncthreads();

    // ---- neigh-half GEMM: o = tid&127, g = tid>>7 (4-way split, 32 k) ----
    {
        const int o = tid & (OUT_DIM - 1);
        const int g = tid >> 7;

        const float* __restrict__ wp =
            W + (size_t)(C_DIM + g * 32) * OUT_DIM + o;
        const float* __restrict__ cb = &combT[C_DIM + g * 32][0];

        unsigned long long a01 = 0ull, a23 = 0ull, a45 = 0ull, a67 = 0ull;

        #pragma unroll 8
        for (int k = 0; k < 32; ++k) {
            float w = wp[(size_t)k * OUT_DIM];
            unsigned long long wpk;
            asm("mov.b64 %0, {%1, %1};" : "=l"(wpk) : "f"(w));

            const double2 q0 = *reinterpret_cast<const double2*>(cb + k * 8);
            const double2 q1 = *reinterpret_cast<const double2*>(cb + k * 8 + 4);
            unsigned long long p01 = __double_as_longlong(q0.x);
            unsigned long long p23 = __double_as_longlong(q0.y);
            unsigned long long p45 = __double_as_longlong(q1.x);
            unsigned long long p67 = __double_as_longlong(q1.y);

            asm("fma.rn.f32x2 %0, %1, %2, %0;" : "+l"(a01) : "l"(p01), "l"(wpk));
            asm("fma.rn.f32x2 %0, %1, %2, %0;" : "+l"(a23) : "l"(p23), "l"(wpk));
            asm("fma.rn.f32x2 %0, %1, %2, %0;" : "+l"(a45) : "l"(p45), "l"(wpk));
            asm("fma.rn.f32x2 %0, %1, %2, %0;" : "+l"(a67) : "l"(p67), "l"(wpk));
        }

        float r0, r1, r2, r3, r4, r5, r6, r7;
        asm("mov.b64 {%0, %1}, %2;" : "=f"(r0), "=f"(r1) : "l"(a01));
        asm("mov.b64 {%0, %1}, %2;" : "=f"(r2), "=f"(r3) : "l"(a23));
        asm("mov.b64 {%0, %1}, %2;" : "=f"(r4), "=f"(r5) : "l"(a45));
        asm("mov.b64 {%0, %1}, %2;" : "=f"(r6), "=f"(r7) : "l"(a67));

        float* p = &ps_ngh[g][0][o];
        p[0 * OUT_DIM] = r0;  p[1 * OUT_DIM] = r1;
        p[2 * OUT_DIM] = r2;  p[3 * OUT_DIM] = r3;
        p[4 * OUT_DIM] = r4;  p[5 * OUT_DIM] = r5;
        p[6 * OUT_DIM] = r6;  p[7 * OUT_DIM] = r7;
    }
    __syncthreads();

    // ---- final reduction: 1024 outputs, 2 per thread ----
    #pragma unroll
    for (int rep = 0; rep < 2; ++rep) {
        const int idx = tid + rep * THREADS;     // row*128 + o
        const int r   = idx >> 7;
        const int o   = idx & (OUT_DIM - 1);
        float sum = bias[o]
                  + ps_feat[0][r][o] + ps_feat[1][r][o]
                  + ps_ngh[0][r][o] + ps_ngh[1][r][o]
                  + ps_ngh[2][r][o] + ps_ngh[3][r][o];
        out[(size_t)block_row0 * OUT_DIM + idx] = sum;
    }
}

extern "C" void kernel_launch(void* const* d_in, const int* in_sizes, int n_in,
                              void* d_out, int out_size)
{
    (void)in_sizes; (void)n_in; (void)out_size;
    const float* adj  = (const float*)d_in[0];   // [B,N,N]
    const float* feat = (const float*)d_in[1];   // [B,N,C]
    const float* W    = (const float*)d_in[2];   // [2C,OUT]
    const float* bias = (const float*)d_in[3];   // [OUT]
    float* out        = (float*)d_out;           // [B,N,OUT]

    dim3 grid((B_DIM * N_DIM) / ROWS);   // 256
    dim3 block(THREADS);                 // 512
    graphsage_fused_kernel<<<grid, block>>>(adj, feat, W, bias, out);
}

// round 11
// speedup vs baseline: 1.1604x; 1.1604x over previous
#include <cuda_runtime.h>
#include <math_constants.h>

// GraphSAGE fused: masked-max aggregation + relu + concat + Linear.
// B=4, N=512, C=128, OUT=128, adj ~10% dense (0.0/1.0 floats).
//
// R11 = R9 (best, 14.5us) with GEMM W-load economy:
//  - each thread computes 8 rows x 2 ADJACENT cols (2o, 2o+1): the two W
//    values per k come from one LDG.64 instead of two LDG.32 (-1 instr/k).
//  - 8-way k-split (32 k/thread), W read exactly once per block,
//    packed fma.rn.f32x2, 32KB smem split-k reduction (all R9-proven).

#define B_DIM 4
#define N_DIM 512
#define C_DIM 128
#define OUT_DIM 128
#define ROWS 8
#define THREADS 512

__global__ __launch_bounds__(THREADS, 2)
void graphsage_fused_kernel(const float* __restrict__ adj,
                            const float* __restrict__ feat,
                            const float* __restrict__ W,
                            const float* __restrict__ bias,
                            float* __restrict__ out)
{
    __shared__ __align__(16) float combT[2 * C_DIM][ROWS];   // 8 KB persistent
    __shared__ __align__(16) char scratch[32768];            // 32 KB aliased

    float (*aggbuf)[2][C_DIM] = reinterpret_cast<float (*)[2][C_DIM]>(scratch);
    unsigned short (*idxbuf)[264] =
        reinterpret_cast<unsigned short (*)[264]>(scratch + 8192);
    float* ps = reinterpret_cast<float*>(scratch);   // [8][ROWS*OUT] partials

    const int tid  = threadIdx.x;
    const int warp = tid >> 5;
    const int lane = tid & 31;
    const int row  = warp >> 1;
    const int half = warp & 1;

    const int block_row0 = blockIdx.x * ROWS;
    const int grow = block_row0 + row;
    const int b = grow >> 9;
    const int i = grow & (N_DIM - 1);

    const float* __restrict__ fb = feat + (size_t)b * N_DIM * C_DIM;

    // ---------------- Phase 1a: compact neighbor indices ----------------
    const float* __restrict__ adjrow =
        adj + ((size_t)b * N_DIM + i) * N_DIM + half * (N_DIM / 2);
    unsigned short* __restrict__ myidx = idxbuf[warp];
    const unsigned lt = (1u << lane) - 1u;

    int total = 0;
    #pragma unroll
    for (int c = 0; c < N_DIM / 2; c += 128) {
        float4 a = reinterpret_cast<const float4*>(adjrow + c)[lane];
        const int cbase = half * (N_DIM / 2) + c + 4 * lane;
        {
            unsigned m = __ballot_sync(0xffffffffu, a.x > 0.0f);
            if (a.x > 0.0f) myidx[total + __popc(m & lt)] = (unsigned short)(cbase + 0);
            total += __popc(m);
        }
        {
            unsigned m = __ballot_sync(0xffffffffu, a.y > 0.0f);
            if (a.y > 0.0f) myidx[total + __popc(m & lt)] = (unsigned short)(cbase + 1);
            total += __popc(m);
        }
        {
            unsigned m = __ballot_sync(0xffffffffu, a.z > 0.0f);
            if (a.z > 0.0f) myidx[total + __popc(m & lt)] = (unsigned short)(cbase + 2);
            total += __popc(m);
        }
        {
            unsigned m = __ballot_sync(0xffffffffu, a.w > 0.0f);
            if (a.w > 0.0f) myidx[total + __popc(m & lt)] = (unsigned short)(cbase + 3);
            total += __popc(m);
        }
    }
    __syncwarp();

    // ---------------- Phase 1b: gather + running max, MLP=8 ----------------
    float4 acc0 = make_float4(-CUDART_INF_F, -CUDART_INF_F, -CUDART_INF_F, -CUDART_INF_F);
    float4 acc1 = acc0, acc2 = acc0, acc3 = acc0;

    if (total > 0) {
        const int padded = (total + 7) & ~7;
        unsigned short lastv = myidx[total - 1];
        __syncwarp();
        if (lane < padded - total) myidx[total + lane] = lastv;
        __syncwarp();

        const uint4* __restrict__ ivec = reinterpret_cast<const uint4*>(myidx);
        for (int k = 0; k < padded; k += 8) {
            uint4 I = ivec[k >> 3];
            int j0 =  I.x        & 0xffff;
            int j1 = (I.x >> 16) & 0xffff;
            int j2 =  I.y        & 0xffff;
            int j3 = (I.y >> 16) & 0xffff;
            int j4 =  I.z        & 0xffff;
            int j5 = (I.z >> 16) & 0xffff;
            int j6 =  I.w        & 0xffff;
            int j7 = (I.w >> 16) & 0xffff;

            float4 f0 = reinterpret_cast<const float4*>(fb + (size_t)j0 * C_DIM)[lane];
            float4 f1 = reinterpret_cast<const float4*>(fb + (size_t)j1 * C_DIM)[lane];
            float4 f2 = reinterpret_cast<const float4*>(fb + (size_t)j2 * C_DIM)[lane];
            float4 f3 = reinterpret_cast<const float4*>(fb + (size_t)j3 * C_DIM)[lane];
            float4 f4 = reinterpret_cast<const float4*>(fb + (size_t)j4 * C_DIM)[lane];
            float4 f5 = reinterpret_cast<const float4*>(fb + (size_t)j5 * C_DIM)[lane];
            float4 f6 = reinterpret_cast<const float4*>(fb + (size_t)j6 * C_DIM)[lane];
            float4 f7 = reinterpret_cast<const float4*>(fb + (size_t)j7 * C_DIM)[lane];

            acc0.x = fmaxf(acc0.x, f0.x); acc0.y = fmaxf(acc0.y, f0.y);
            acc0.z = fmaxf(acc0.z, f0.z); acc0.w = fmaxf(acc0.w, f0.w);
            acc1.x = fmaxf(acc1.x, f1.x); acc1.y = fmaxf(acc1.y, f1.y);
            acc1.z = fmaxf(acc1.z, f1.z); acc1.w = fmaxf(acc1.w, f1.w);
            acc2.x = fmaxf(acc2.x, f2.x); acc2.y = fmaxf(acc2.y, f2.y);
            acc2.z = fmaxf(acc2.z, f2.z); acc2.w = fmaxf(acc2.w, f2.w);
            acc3.x = fmaxf(acc3.x, f3.x); acc3.y = fmaxf(acc3.y, f3.y);
            acc3.z = fmaxf(acc3.z, f3.z); acc3.w = fmaxf(acc3.w, f3.w);

            acc0.x = fmaxf(acc0.x, f4.x); acc0.y = fmaxf(acc0.y, f4.y);
            acc0.z = fmaxf(acc0.z, f4.z); acc0.w = fmaxf(acc0.w, f4.w);
            acc1.x = fmaxf(acc1.x, f5.x); acc1.y = fmaxf(acc1.y, f5.y);
            acc1.z = fmaxf(acc1.z, f5.z); acc1.w = fmaxf(acc1.w, f5.w);
            acc2.x = fmaxf(acc2.x, f6.x); acc2.y = fmaxf(acc2.y, f6.y);
            acc2.z = fmaxf(acc2.z, f6.z); acc2.w = fmaxf(acc2.w, f6.w);
            acc3.x = fmaxf(acc3.x, f7.x); acc3.y = fmaxf(acc3.y, f7.y);
            acc3.z = fmaxf(acc3.z, f7.z); acc3.w = fmaxf(acc3.w, f7.w);
        }
    }

    float4 accA;
    accA.x = fmaxf(fmaxf(acc0.x, acc1.x), fmaxf(acc2.x, acc3.x));
    accA.y = fmaxf(fmaxf(acc0.y, acc1.y), fmaxf(acc2.y, acc3.y));
    accA.z = fmaxf(fmaxf(acc0.z, acc1.z), fmaxf(acc2.z, acc3.z));
    accA.w = fmaxf(fmaxf(acc0.w, acc1.w), fmaxf(acc2.w, acc3.w));
    reinterpret_cast<float4*>(&aggbuf[row][half][0])[lane] = accA;

    __syncthreads();

    // ---- Phase 1c: build combT (feature copy + combine halves + relu) ----
    {
        const int r  = tid & 7;
        const int c8 = tid >> 3;
        const int gr = block_row0 + r;
        const int rb = gr >> 9;
        const int ri = gr & (N_DIM - 1);
        const float* __restrict__ frow =
            feat + ((size_t)rb * N_DIM + ri) * C_DIM;
        #pragma unroll
        for (int j = 0; j < 2; ++j) {
            const int c = c8 + 64 * j;
            combT[c][r] = frow[c];
            combT[C_DIM + c][r] =
                fmaxf(0.0f, fmaxf(aggbuf[r][0][c], aggbuf[r][1][c]));
        }
    }
    __syncthreads();

    // ---------------- Phase 2: fused linear layer ----------------
    // thread t: op = (t&63)*2 -> cols (op, op+1); g = t>>6 (8-way k-split,
    // 32 k each). 8 rows x 2 adjacent cols; W pair = one LDG.64 per k.
    {
        const int op = (tid & 63) * 2;
        const int g  = tid >> 6;

        const float2* __restrict__ wp = reinterpret_cast<const float2*>(
            W + (size_t)(g * 32) * OUT_DIM + op);
        const float* __restrict__ cb = &combT[g * 32][0];

        unsigned long long a01_0 = 0ull, a23_0 = 0ull, a45_0 = 0ull, a67_0 = 0ull;
        unsigned long long a01_1 = 0ull, a23_1 = 0ull, a45_1 = 0ull, a67_1 = 0ull;

        #pragma unroll 8
        for (int k = 0; k < 32; ++k) {
            float2 w = wp[(size_t)k * (OUT_DIM / 2)];
            unsigned long long wpk0, wpk1;
            asm("mov.b64 %0, {%1, %1};" : "=l"(wpk0) : "f"(w.x));
            asm("mov.b64 %0, {%1, %1};" : "=l"(wpk1) : "f"(w.y));

            const double2 q0 = *reinterpret_cast<const double2*>(cb + k * 8);
            const double2 q1 = *reinterpret_cast<const double2*>(cb + k * 8 + 4);
            unsigned long long p01 = __double_as_longlong(q0.x);
            unsigned long long p23 = __double_as_longlong(q0.y);
            unsigned long long p45 = __double_as_longlong(q1.x);
            unsigned long long p67 = __double_as_longlong(q1.y);

            asm("fma.rn.f32x2 %0, %1, %2, %0;" : "+l"(a01_0) : "l"(p01), "l"(wpk0));
            asm("fma.rn.f32x2 %0, %1, %2, %0;" : "+l"(a23_0) : "l"(p23), "l"(wpk0));
            asm("fma.rn.f32x2 %0, %1, %2, %0;" : "+l"(a45_0) : "l"(p45), "l"(wpk0));
            asm("fma.rn.f32x2 %0, %1, %2, %0;" : "+l"(a67_0) : "l"(p67), "l"(wpk0));
            asm("fma.rn.f32x2 %0, %1, %2, %0;" : "+l"(a01_1) : "l"(p01), "l"(wpk1));
            asm("fma.rn.f32x2 %0, %1, %2, %0;" : "+l"(a23_1) : "l"(p23), "l"(wpk1));
            asm("fma.rn.f32x2 %0, %1, %2, %0;" : "+l"(a45_1) : "l"(p45), "l"(wpk1));
            asm("fma.rn.f32x2 %0, %1, %2, %0;" : "+l"(a67_1) : "l"(p67), "l"(wpk1));
        }

        float r0, r1, r2, r3, r4, r5, r6, r7;
        float s0, s1, s2, s3, s4, s5, s6, s7;
        asm("mov.b64 {%0, %1}, %2;" : "=f"(r0), "=f"(r1) : "l"(a01_0));
        asm("mov.b64 {%0, %1}, %2;" : "=f"(r2), "=f"(r3) : "l"(a23_0));
        asm("mov.b64 {%0, %1}, %2;" : "=f"(r4), "=f"(r5) : "l"(a45_0));
        asm("mov.b64 {%0, %1}, %2;" : "=f"(r6), "=f"(r7) : "l"(a67_0));
        asm("mov.b64 {%0, %1}, %2;" : "=f"(s0), "=f"(s1) : "l"(a01_1));
        asm("mov.b64 {%0, %1}, %2;" : "=f"(s2), "=f"(s3) : "l"(a23_1));
        asm("mov.b64 {%0, %1}, %2;" : "=f"(s4), "=f"(s5) : "l"(a45_1));
        asm("mov.b64 {%0, %1}, %2;" : "=f"(s6), "=f"(s7) : "l"(a67_1));

        // partials: ps[g][row*128 + op(+1)]
        float* p = ps + (size_t)g * (ROWS * OUT_DIM) + op;
        p[0 * OUT_DIM] = r0;  p[1 * OUT_DIM] = r1;
        p[2 * OUT_DIM] = r2;  p[3 * OUT_DIM] = r3;
        p[4 * OUT_DIM] = r4;  p[5 * OUT_DIM] = r5;
        p[6 * OUT_DIM] = r6;  p[7 * OUT_DIM] = r7;
        p[0 * OUT_DIM + 1] = s0;  p[1 * OUT_DIM + 1] = s1;
        p[2 * OUT_DIM + 1] = s2;  p[3 * OUT_DIM + 1] = s3;
        p[4 * OUT_DIM + 1] = s4;  p[5 * OUT_DIM + 1] = s5;
        p[6 * OUT_DIM + 1] = s6;  p[7 * OUT_DIM + 1] = s7;

        __syncthreads();

        // final reduction: 1024 outputs, 2 per thread
        #pragma unroll
        for (int rep = 0; rep < 2; ++rep) {
            const int idx = tid + rep * THREADS;      // row*128 + o
            float sum = bias[idx & (OUT_DIM - 1)];
            #pragma unroll
            for (int gg = 0; gg < 8; ++gg)
                sum += ps[(size_t)gg * (ROWS * OUT_DIM) + idx];
            out[(size_t)block_row0 * OUT_DIM + idx] = sum;
        }
    }
}

extern "C" void kernel_launch(void* const* d_in, const int* in_sizes, int n_in,
                              void* d_out, int out_size)
{
    (void)in_sizes; (void)n_in; (void)out_size;
    const float* adj  = (const float*)d_in[0];   // [B,N,N]
    const float* feat = (const float*)d_in[1];   // [B,N,C]
    const float* W    = (const float*)d_in[2];   // [2C,OUT]
    const float* bias = (const float*)d_in[3];   // [OUT]
    float* out        = (float*)d_out;           // [B,N,OUT]

    dim3 grid((B_DIM * N_DIM) / ROWS);   // 256
    dim3 block(THREADS);                 // 512
    graphsage_fused_kernel<<<grid, block>>>(adj, feat, W, bias, out);
}